// round 8
// baseline (speedup 1.0000x reference)
#include <cuda_runtime.h>
#include <cuda_fp16.h>

#define N_NODESC 100000
#define N_EDGESC 1600000
#define IN_CH    128
#define NH       64
#define NH2      32
#define OUT_CHC  40

#define SCAN_CHUNK 1024
#define SCAN_NBLK  ((N_NODESC + SCAN_CHUNK - 1) / SCAN_CHUNK)   // 98

typedef unsigned long long u64b;

// ---------------- f32x2 packed helpers (bit-exact fp32, 2 MACs/instr) ----------------
__device__ __forceinline__ void ffma2(u64b& d, u64b a, u64b b) {
    asm("fma.rn.f32x2 %0, %1, %2, %0;" : "+l"(d) : "l"(a), "l"(b));
}
__device__ __forceinline__ float2 unpack2(u64b v) {
    float2 f; asm("mov.b64 {%0, %1}, %2;" : "=f"(f.x), "=f"(f.y) : "l"(v)); return f;
}
union F4U { float4 v; u64b d[2]; };

// ---------------- scratch ----------------
__device__ int     g_is64;
__device__ int     g_deg[N_NODESC];
__device__ int     g_rowptr[N_NODESC + 1];
__device__ int     g_cursor[N_NODESC];
__device__ int     g_bsum[SCAN_NBLK];
__device__ int     g_boff[SCAN_NBLK];
__device__ int     g_row32[N_EDGESC];
__device__ int     g_col32[N_EDGESC];
__device__ int     g_src[N_EDGESC];
__device__ float   g_dinv[N_NODESC];
__device__ float   g_h0[N_NODESC * NH];          // fp32 residual path (unscaled)
__device__ __half2 g_h016[N_NODESC * NH2];       // fp16, pre-scaled by dinv[node]
__device__ __half2 g_hA16[N_NODESC * NH2];
__device__ __half2 g_hB16[N_NODESC * NH2];

// ---------------- dtype detect + zero degree ----------------
__global__ void k_init(const int* __restrict__ ei) {
    int i = blockIdx.x * blockDim.x + threadIdx.x;
    if (i < N_NODESC) g_deg[i] = 0;
    if (blockIdx.x == 0 && threadIdx.x == 0) {
        int nz = 0;
        for (int j = 1; j < 512; j += 2) nz |= ei[j];
        g_is64 = (nz == 0) ? 1 : 0;
    }
}

// 2 edges per thread
__global__ void k_degree(const int* __restrict__ ei) {
    int t = blockIdx.x * blockDim.x + threadIdx.x;
    if (t >= N_EDGESC / 2) return;
    int r0, c0, r1, c1;
    if (g_is64) {
        int4 rr = __ldg((const int4*)&ei[4 * t]);
        int4 cc = __ldg((const int4*)&ei[2 * N_EDGESC + 4 * t]);
        r0 = rr.x; r1 = rr.z; c0 = cc.x; c1 = cc.z;
    } else {
        int2 rr = __ldg((const int2*)&ei[2 * t]);
        int2 cc = __ldg((const int2*)&ei[N_EDGESC + 2 * t]);
        r0 = rr.x; r1 = rr.y; c0 = cc.x; c1 = cc.y;
    }
    if ((unsigned)r0 >= N_NODESC) r0 = 0;
    if ((unsigned)r1 >= N_NODESC) r1 = 0;
    if ((unsigned)c0 >= N_NODESC) c0 = 0;
    if ((unsigned)c1 >= N_NODESC) c1 = 0;
    *(int2*)&g_row32[2 * t] = make_int2(r0, r1);
    *(int2*)&g_col32[2 * t] = make_int2(c0, c1);
    atomicAdd(&g_deg[c0], 1);
    atomicAdd(&g_deg[c1], 1);
}

__global__ void k_scan_bsum() {
    __shared__ int s[SCAN_CHUNK];
    int t = threadIdx.x;
    int i = blockIdx.x * SCAN_CHUNK + t;
    int d = (i < N_NODESC) ? g_deg[i] : 0;
    if (i < N_NODESC) g_dinv[i] = (d > 0) ? rsqrtf((float)d) : 0.0f;
    s[t] = d;
    __syncthreads();
    for (int off = SCAN_CHUNK / 2; off > 0; off >>= 1) {
        if (t < off) s[t] += s[t + off];
        __syncthreads();
    }
    if (t == 0) g_bsum[blockIdx.x] = s[0];
}

__global__ void k_scan_top() {
    __shared__ int s[128];
    int t = threadIdx.x;
    s[t] = (t < SCAN_NBLK) ? g_bsum[t] : 0;
    __syncthreads();
    if (t == 0) {
        int acc = 0;
        for (int b = 0; b < SCAN_NBLK; b++) { int v = s[b]; s[b] = acc; acc += v; }
        g_rowptr[N_NODESC] = N_EDGESC;
    }
    __syncthreads();
    if (t < SCAN_NBLK) g_boff[t] = s[t];
}

__global__ void k_scan_within() {
    __shared__ int s[SCAN_CHUNK];
    int t = threadIdx.x;
    int i = blockIdx.x * SCAN_CHUNK + t;
    int v = (i < N_NODESC) ? g_deg[i] : 0;
    s[t] = v;
    __syncthreads();
    for (int off = 1; off < SCAN_CHUNK; off <<= 1) {
        int x = (t >= off) ? s[t - off] : 0;
        __syncthreads();
        s[t] += x;
        __syncthreads();
    }
    int excl = s[t] - v + g_boff[blockIdx.x];
    if (i < N_NODESC) { g_rowptr[i] = excl; g_cursor[i] = excl; }
}

// 2 edges per thread; src index only (norm folded into fp16 values)
__global__ void k_scatter() {
    int t = blockIdx.x * blockDim.x + threadIdx.x;
    if (t >= N_EDGESC / 2) return;
    int2 rr = *(const int2*)&g_row32[2 * t];
    int2 cc = *(const int2*)&g_col32[2 * t];
    int p0 = atomicAdd(&g_cursor[cc.x], 1);
    if ((unsigned)p0 < N_EDGESC) g_src[p0] = rr.x;
    int p1 = atomicAdd(&g_cursor[cc.y], 1);
    if ((unsigned)p1 < N_EDGESC) g_src[p1] = rr.y;
}

// ---------------- fc1: h = relu(x @ W1^T + b1) ----------------
#define FC1_TILE 64
__global__ __launch_bounds__(256) void k_fc1(const float* __restrict__ x,
                                             const float* __restrict__ w,
                                             const float* __restrict__ b) {
    __shared__ float  sW[NH * IN_CH];       // 32 KB, [j][k] (broadcast reads)
    __shared__ float4 sX[FC1_TILE * 32];    // 32 KB, [node][(u+node)&31]
    for (int i = threadIdx.x; i < NH * IN_CH; i += 256) sW[i] = w[i];

    int warp = threadIdx.x >> 5, lane = threadIdx.x & 31;
    int j0 = warp * 8;
    float4 b0 = __ldg((const float4*)&b[j0]);
    float4 b1 = __ldg((const float4*)&b[j0 + 4]);
    float bias[8] = {b0.x, b0.y, b0.z, b0.w, b1.x, b1.y, b1.z, b1.w};

    const int ntiles = (N_NODESC + FC1_TILE - 1) / FC1_TILE;    // 1563
    for (int tile = blockIdx.x; tile < ntiles; tile += gridDim.x) {
        int base = tile * FC1_TILE;
        __syncthreads();
        {   // stage 64 nodes, rotated rows; clamp OOB rows to node 0 of tile
            int n = threadIdx.x >> 2;           // 0..63
            int u0 = threadIdx.x & 3;
            long row = (base + n < N_NODESC) ? (long)(base + n) : (long)base;
            #pragma unroll
            for (int it = 0; it < 8; it++) {
                int u = u0 + 4 * it;
                float4 v = __ldg((const float4*)&x[row * IN_CH + u * 4]);
                sX[n * 32 + ((u + n) & 31)] = v;
            }
        }
        __syncthreads();

        int nA = lane, nB = lane + 32;
        u64b accA[8], accB[8];
        #pragma unroll
        for (int q = 0; q < 8; q++) { accA[q] = 0ULL; accB[q] = 0ULL; }

        #pragma unroll 4
        for (int kq = 0; kq < 32; kq++) {
            F4U xa; xa.v = sX[nA * 32 + ((kq + nA) & 31)];
            F4U xb; xb.v = sX[nB * 32 + ((kq + nB) & 31)];
            #pragma unroll
            for (int q = 0; q < 8; q++) {
                F4U wv; wv.v = *(const float4*)&sW[(j0 + q) * IN_CH + kq * 4];
                ffma2(accA[q], xa.d[0], wv.d[0]);
                ffma2(accA[q], xa.d[1], wv.d[1]);
                ffma2(accB[q], xb.d[0], wv.d[0]);
                ffma2(accB[q], xb.d[1], wv.d[1]);
            }
        }

        #pragma unroll
        for (int half = 0; half < 2; half++) {
            int node = base + (half ? nB : nA);
            if (node >= N_NODESC) continue;
            u64b* acc = half ? accB : accA;
            float dv = g_dinv[node];
            float r[8];
            #pragma unroll
            for (int q = 0; q < 8; q++) {
                float2 f = unpack2(acc[q]);
                r[q] = fmaxf(f.x + f.y + bias[q], 0.f);
            }
            *(float4*)&g_h0[(long)node * NH + j0]     = make_float4(r[0], r[1], r[2], r[3]);
            *(float4*)&g_h0[(long)node * NH + j0 + 4] = make_float4(r[4], r[5], r[6], r[7]);
            __half2 hh[4];
            #pragma unroll
            for (int q = 0; q < 4; q++)
                hh[q] = __floats2half2_rn(r[2 * q] * dv, r[2 * q + 1] * dv);
            *(uint2*)&g_h016[node * NH2 + (j0 >> 1)]     = *(uint2*)&hh[0];
            *(uint2*)&g_h016[node * NH2 + (j0 >> 1) + 2] = *(uint2*)&hh[2];
        }
    }
}

// ---------------- fused GCN2 layer: 64-node blocks ----------------
// Gather: half-warp per edge (lanes 0-15 edge 2p, 16-31 edge 2p+1); each lane
// loads uint2 = 4 channels; one warp-LDG covers 2 edges. Odd CSR segment start
// is peeled as a scalar head so the int2 pair loop is always 8B-aligned.
__global__ __launch_bounds__(256) void k_layer(const __half2* __restrict__ hin2,
                                               const float* __restrict__ h0,
                                               const float* __restrict__ W,
                                               __half2* __restrict__ hout2,
                                               int scale_out) {
    __shared__ float4 sW4[32 * 32];     // 16 KB packed W
    __shared__ float2 sMixT[32 * 66];   // 16.9 KB: [kp][n]

    for (int i = threadIdx.x; i < NH * NH; i += 256) {
        int k = i >> 6, j = i & 63;     // W row-major [k][j]
        int j2 = j >> 1, kp = k >> 1;
        int sel = ((j & 1) << 1) | (k & 1);
        ((float*)sW4)[j2 * 128 + (((kp + j2) & 31) << 2) + sel] = W[i];
    }

    int warp = threadIdx.x >> 5, lane = threadIdx.x & 31;
    int half  = lane >> 4;              // 0/1: which edge of the pair
    int chunk = lane & 15;              // uint2 index within row (4 channels)
    int nodebase = blockIdx.x * 64;
    const uint2* hin4 = (const uint2*)hin2;     // 16 uint2 per node row

    // gather 8 nodes per warp
    for (int m = 0; m < 8; m++) {
        int nl = warp * 8 + m;
        int node = nodebase + nl;
        float a0 = 0.f, a1 = 0.f, a2 = 0.f, a3 = 0.f;
        if (node < N_NODESC) {
            int s = g_rowptr[node], e = g_rowptr[node + 1];
            int i = s;
            if ((i & 1) && i < e) {     // peel odd head (scalar, lanes 0-15)
                if (half == 0) {
                    int src = __ldg(&g_src[i]);
                    uint2 raw = __ldg(&hin4[src * 16 + chunk]);
                    float2 f0 = __half22float2(*(__half2*)&raw.x);
                    float2 f1 = __half22float2(*(__half2*)&raw.y);
                    a0 += f0.x; a1 += f0.y; a2 += f1.x; a3 += f1.y;
                }
                i++;
            }
            int npairs = (e - i) >> 1;  // i now even -> int2 loads 8B-aligned
            #pragma unroll 4
            for (int p = 0; p < npairs; p++) {
                int2 ss = __ldg((const int2*)&g_src[i + 2 * p]);
                int src = half ? ss.y : ss.x;
                uint2 raw = __ldg(&hin4[src * 16 + chunk]);
                float2 f0 = __half22float2(*(__half2*)&raw.x);
                float2 f1 = __half22float2(*(__half2*)&raw.y);
                a0 += f0.x; a1 += f0.y; a2 += f1.x; a3 += f1.y;
            }
            if ((e - i) & 1) {          // scalar tail (lanes 0-15)
                if (half == 0) {
                    int src = __ldg(&g_src[e - 1]);
                    uint2 raw = __ldg(&hin4[src * 16 + chunk]);
                    float2 f0 = __half22float2(*(__half2*)&raw.x);
                    float2 f1 = __half22float2(*(__half2*)&raw.y);
                    a0 += f0.x; a1 += f0.y; a2 += f1.x; a3 += f1.y;
                }
            }
        }
        // combine both halves: lanes 0-15 end with full channel sums
        a0 += __shfl_xor_sync(0xffffffffu, a0, 16);
        a1 += __shfl_xor_sync(0xffffffffu, a1, 16);
        a2 += __shfl_xor_sync(0xffffffffu, a2, 16);
        a3 += __shfl_xor_sync(0xffffffffu, a3, 16);

        if (half == 0) {
            float mx0 = 0.f, my0 = 0.f, mx1 = 0.f, my1 = 0.f;
            if (node < N_NODESC) {
                float4 h0v = *(const float4*)&h0[(long)node * NH + 4 * chunk];
                float dv = g_dinv[node];
                mx0 = fmaf(0.9f * dv, a0, 0.1f * h0v.x);
                my0 = fmaf(0.9f * dv, a1, 0.1f * h0v.y);
                mx1 = fmaf(0.9f * dv, a2, 0.1f * h0v.z);
                my1 = fmaf(0.9f * dv, a3, 0.1f * h0v.w);
            }
            sMixT[(2 * chunk) * 66 + nl]     = make_float2(mx0, my0);
            sMixT[(2 * chunk + 1) * 66 + nl] = make_float2(mx1, my1);
        }
        __syncwarp();
    }
    __syncthreads();

    // matmul
    int j2 = lane, nq = warp;
    u64b acc0[8], acc1[8];
    #pragma unroll
    for (int n = 0; n < 8; n++) { acc0[n] = 0ULL; acc1[n] = 0ULL; }

    #pragma unroll 4
    for (int kp = 0; kp < 32; kp++) {
        F4U wv; wv.v = sW4[j2 * 32 + ((kp + j2) & 31)];
        const float2* mrow = &sMixT[kp * 66 + nq * 8];
        #pragma unroll
        for (int p = 0; p < 4; p++) {
            F4U mp; mp.v = *(const float4*)&mrow[2 * p];
            ffma2(acc0[2 * p],     mp.d[0], wv.d[0]);
            ffma2(acc1[2 * p],     mp.d[0], wv.d[1]);
            ffma2(acc0[2 * p + 1], mp.d[1], wv.d[0]);
            ffma2(acc1[2 * p + 1], mp.d[1], wv.d[1]);
        }
    }

    #pragma unroll
    for (int n = 0; n < 8; n++) {
        int node = nodebase + nq * 8 + n;
        if (node < N_NODESC) {
            float2 f0 = unpack2(acc0[n]);
            float2 f1 = unpack2(acc1[n]);
            float o0 = fmaxf(f0.x + f0.y, 0.f);
            float o1 = fmaxf(f1.x + f1.y, 0.f);
            float sc = scale_out ? g_dinv[node] : 1.0f;
            hout2[node * NH2 + j2] = __floats2half2_rn(o0 * sc, o1 * sc);
        }
    }
}

// ---------------- fc2: out = h @ W2^T + b2, split-K f32x2 ----------------
#define SW2S 66
#define SH2S 66
__global__ __launch_bounds__(320, 4) void k_fc2(const __half2* __restrict__ hin2,
                                                const float* __restrict__ w,
                                                const float* __restrict__ b,
                                                float* __restrict__ out) {
    __shared__ float sW[OUT_CHC * SW2S];
    __shared__ float sH[8 * SH2S];
    __shared__ float sB[OUT_CHC];
    for (int i = threadIdx.x; i < OUT_CHC * NH / 2; i += 320) {
        int j = i >> 5, kp = i & 31;
        *(float2*)&sW[j * SW2S + 2 * kp] = *(const float2*)&w[j * NH + 2 * kp];
    }
    if (threadIdx.x < OUT_CHC) sB[threadIdx.x] = b[threadIdx.x];
    __syncthreads();

    int tn = threadIdx.x / OUT_CHC;
    int j  = threadIdx.x % OUT_CHC;
    const int ngroups = N_NODESC / 8;

    for (int g = blockIdx.x; g < ngroups; g += gridDim.x) {
        int base = g * 8;
        __syncthreads();
        for (int i = threadIdx.x; i < 8 * NH2; i += 320) {
            int n = i >> 5, k2 = i & 31;
            float2 v = __half22float2(hin2[(base + n) * NH2 + k2]);
            *(float2*)&sH[n * SH2S + 2 * k2] = v;
        }
        __syncthreads();
        u64b acc = 0ULL;
        #pragma unroll 8
        for (int kp = 0; kp < NH / 2; kp++) {
            u64b a  = *(const u64b*)&sH[tn * SH2S + 2 * kp];
            u64b wv = *(const u64b*)&sW[j * SW2S + 2 * kp];
            ffma2(acc, a, wv);
        }
        float2 f = unpack2(acc);
        out[(long)(base + tn) * OUT_CHC + j] = f.x + f.y + sB[j];
    }
}

// ---------------- launch ----------------
extern "C" void kernel_launch(void* const* d_in, const int* in_sizes, int n_in,
                              void* d_out, int out_size) {
    const float* x      = (const float*)d_in[0];
    const int*   ei     = (const int*)d_in[1];
    const float* fc1_w  = (const float*)d_in[3];
    const float* fc1_b  = (const float*)d_in[4];
    const float* conv_w = (const float*)d_in[5];
    const float* fc2_w  = (const float*)d_in[6];
    const float* fc2_b  = (const float*)d_in[7];
    float*       out    = (float*)d_out;

    const int nb_nodes  = (N_NODESC + 255) / 256;
    const int nb_epairs = (N_EDGESC / 2 + 255) / 256;

    k_init<<<nb_nodes, 256>>>(ei);              // 0
    k_degree<<<nb_epairs, 256>>>(ei);           // 1
    k_scan_bsum<<<SCAN_NBLK, SCAN_CHUNK>>>();   // 2 (also dinv)
    k_fc1<<<1563, 256>>>(x, fc1_w, fc1_b);      // 3 (profiled slot)
    k_scan_top<<<1, 128>>>();
    k_scan_within<<<SCAN_NBLK, SCAN_CHUNK>>>();
    k_scatter<<<nb_epairs, 256>>>();

    float* h0; __half2* h016; __half2* hA16; __half2* hB16;
    cudaGetSymbolAddress((void**)&h0,   g_h0);
    cudaGetSymbolAddress((void**)&h016, g_h016);
    cudaGetSymbolAddress((void**)&hA16, g_hA16);
    cudaGetSymbolAddress((void**)&hB16, g_hB16);

    const int nb_layer = (N_NODESC + 63) / 64;  // 1563
    k_layer<<<nb_layer, 256>>>(h016, h0, conv_w + 0 * NH * NH, hA16, 1);
    k_layer<<<nb_layer, 256>>>(hA16, h0, conv_w + 1 * NH * NH, hB16, 1);
    k_layer<<<nb_layer, 256>>>(hB16, h0, conv_w + 2 * NH * NH, hA16, 1);
    k_layer<<<nb_layer, 256>>>(hA16, h0, conv_w + 3 * NH * NH, hB16, 0);

    k_fc2<<<592, 320>>>(hB16, fc2_w, fc2_b, out);
}

// round 9
// speedup vs baseline: 1.0308x; 1.0308x over previous
#include <cuda_runtime.h>
#include <cuda_fp16.h>

#define N_NODESC 100000
#define N_EDGESC 1600000
#define IN_CH    128
#define NH       64
#define NH2      32
#define OUT_CHC  40

#define SCAN_CHUNK 1024
#define SCAN_NBLK  ((N_NODESC + SCAN_CHUNK - 1) / SCAN_CHUNK)   // 98

typedef unsigned long long u64b;

// ---------------- f32x2 packed helpers (bit-exact fp32, 2 MACs/instr) ----------------
__device__ __forceinline__ void ffma2(u64b& d, u64b a, u64b b) {
    asm("fma.rn.f32x2 %0, %1, %2, %0;" : "+l"(d) : "l"(a), "l"(b));
}
__device__ __forceinline__ float2 unpack2(u64b v) {
    float2 f; asm("mov.b64 {%0, %1}, %2;" : "=f"(f.x), "=f"(f.y) : "l"(v)); return f;
}
union F4U { float4 v; u64b d[2]; };

// ---------------- scratch ----------------
__device__ int     g_is64;
__device__ int     g_deg[N_NODESC];
__device__ int     g_rowptr[N_NODESC + 1];
__device__ int     g_cursor[N_NODESC];
__device__ int     g_bsum[SCAN_NBLK];
__device__ int     g_boff[SCAN_NBLK];
__device__ int     g_src[N_EDGESC];
__device__ float   g_dinv[N_NODESC];
__device__ float   g_h0[N_NODESC * NH];          // fp32 residual path (unscaled)
__device__ __half2 g_h016[N_NODESC * NH2];       // fp16, pre-scaled by dinv[node]
__device__ __half2 g_hA16[N_NODESC * NH2];
__device__ __half2 g_hB16[N_NODESC * NH2];

// ---------------- dtype detect + zero degree ----------------
__global__ void k_init(const int* __restrict__ ei) {
    int i = blockIdx.x * blockDim.x + threadIdx.x;
    if (i < N_NODESC) g_deg[i] = 0;
    if (blockIdx.x == 0 && threadIdx.x == 0) {
        int nz = 0;
        for (int j = 1; j < 512; j += 2) nz |= ei[j];
        g_is64 = (nz == 0) ? 1 : 0;
    }
}

// decode 2 edges per thread; histogram only (no row/col store)
__global__ void k_degree(const int* __restrict__ ei) {
    int t = blockIdx.x * blockDim.x + threadIdx.x;
    if (t >= N_EDGESC / 2) return;
    int c0, c1;
    if (g_is64) {
        int4 cc = __ldg((const int4*)&ei[2 * N_EDGESC + 4 * t]);
        c0 = cc.x; c1 = cc.z;
    } else {
        int2 cc = __ldg((const int2*)&ei[N_EDGESC + 2 * t]);
        c0 = cc.x; c1 = cc.y;
    }
    if ((unsigned)c0 >= N_NODESC) c0 = 0;
    if ((unsigned)c1 >= N_NODESC) c1 = 0;
    atomicAdd(&g_deg[c0], 1);
    atomicAdd(&g_deg[c1], 1);
}

__global__ void k_scan_bsum() {
    __shared__ int s[SCAN_CHUNK];
    int t = threadIdx.x;
    int i = blockIdx.x * SCAN_CHUNK + t;
    int d = (i < N_NODESC) ? g_deg[i] : 0;
    if (i < N_NODESC) g_dinv[i] = (d > 0) ? rsqrtf((float)d) : 0.0f;
    s[t] = d;
    __syncthreads();
    for (int off = SCAN_CHUNK / 2; off > 0; off >>= 1) {
        if (t < off) s[t] += s[t + off];
        __syncthreads();
    }
    if (t == 0) g_bsum[blockIdx.x] = s[0];
}

__global__ void k_scan_top() {
    __shared__ int s[128];
    int t = threadIdx.x;
    s[t] = (t < SCAN_NBLK) ? g_bsum[t] : 0;
    __syncthreads();
    if (t == 0) {
        int acc = 0;
        for (int b = 0; b < SCAN_NBLK; b++) { int v = s[b]; s[b] = acc; acc += v; }
        g_rowptr[N_NODESC] = N_EDGESC;
    }
    __syncthreads();
    if (t < SCAN_NBLK) g_boff[t] = s[t];
}

__global__ void k_scan_within() {
    __shared__ int s[SCAN_CHUNK];
    int t = threadIdx.x;
    int i = blockIdx.x * SCAN_CHUNK + t;
    int v = (i < N_NODESC) ? g_deg[i] : 0;
    s[t] = v;
    __syncthreads();
    for (int off = 1; off < SCAN_CHUNK; off <<= 1) {
        int x = (t >= off) ? s[t - off] : 0;
        __syncthreads();
        s[t] += x;
        __syncthreads();
    }
    int excl = s[t] - v + g_boff[blockIdx.x];
    if (i < N_NODESC) { g_rowptr[i] = excl; g_cursor[i] = excl; }
}

// decode 2 edges per thread directly from ei; src index only
__global__ void k_scatter(const int* __restrict__ ei) {
    int t = blockIdx.x * blockDim.x + threadIdx.x;
    if (t >= N_EDGESC / 2) return;
    int r0, c0, r1, c1;
    if (g_is64) {
        int4 rr = __ldg((const int4*)&ei[4 * t]);
        int4 cc = __ldg((const int4*)&ei[2 * N_EDGESC + 4 * t]);
        r0 = rr.x; r1 = rr.z; c0 = cc.x; c1 = cc.z;
    } else {
        int2 rr = __ldg((const int2*)&ei[2 * t]);
        int2 cc = __ldg((const int2*)&ei[N_EDGESC + 2 * t]);
        r0 = rr.x; r1 = rr.y; c0 = cc.x; c1 = cc.y;
    }
    if ((unsigned)r0 >= N_NODESC) r0 = 0;
    if ((unsigned)r1 >= N_NODESC) r1 = 0;
    if ((unsigned)c0 >= N_NODESC) c0 = 0;
    if ((unsigned)c1 >= N_NODESC) c1 = 0;
    int p0 = atomicAdd(&g_cursor[c0], 1);
    if ((unsigned)p0 < N_EDGESC) g_src[p0] = r0;
    int p1 = atomicAdd(&g_cursor[c1], 1);
    if ((unsigned)p1 < N_EDGESC) g_src[p1] = r1;
}

// ---------------- fc1: h = relu(x @ W1^T + b1) ----------------
// 512 threads = 16 warps; warp w: j0 = (w&7)*8, node = lane + 32*(w>>3).
// 64-node tile; thread: 1 node x 8 outputs. 3 blocks/SM -> 48 warps (75% occ).
#define FC1_TILE 64
__global__ __launch_bounds__(512) void k_fc1(const float* __restrict__ x,
                                             const float* __restrict__ w,
                                             const float* __restrict__ b) {
    __shared__ float  sW[NH * IN_CH];       // 32 KB, [j][k] (broadcast reads)
    __shared__ float4 sX[FC1_TILE * 32];    // 32 KB, [node][(u+node)&31]
    for (int i = threadIdx.x; i < NH * IN_CH; i += 512) sW[i] = w[i];

    int warp = threadIdx.x >> 5, lane = threadIdx.x & 31;
    int j0 = (warp & 7) * 8;
    int nloc = lane + 32 * (warp >> 3);     // 0..63
    float4 b0 = __ldg((const float4*)&b[j0]);
    float4 b1 = __ldg((const float4*)&b[j0 + 4]);
    float bias[8] = {b0.x, b0.y, b0.z, b0.w, b1.x, b1.y, b1.z, b1.w};

    const int ntiles = (N_NODESC + FC1_TILE - 1) / FC1_TILE;    // 1563
    for (int tile = blockIdx.x; tile < ntiles; tile += gridDim.x) {
        int base = tile * FC1_TILE;
        __syncthreads();
        {   // stage 64 nodes, rotated rows; clamp OOB rows to tile start
            int n = threadIdx.x >> 3;           // 0..63
            int u0 = threadIdx.x & 7;
            long row = (base + n < N_NODESC) ? (long)(base + n) : (long)base;
            #pragma unroll
            for (int it = 0; it < 4; it++) {
                int u = u0 + 8 * it;
                float4 v = __ldg((const float4*)&x[row * IN_CH + u * 4]);
                sX[n * 32 + ((u + n) & 31)] = v;
            }
        }
        __syncthreads();

        u64b acc[8];
        #pragma unroll
        for (int q = 0; q < 8; q++) acc[q] = 0ULL;

        #pragma unroll 4
        for (int kq = 0; kq < 32; kq++) {
            F4U xv; xv.v = sX[nloc * 32 + ((kq + nloc) & 31)];
            #pragma unroll
            for (int q = 0; q < 8; q++) {
                F4U wv; wv.v = *(const float4*)&sW[(j0 + q) * IN_CH + kq * 4];
                ffma2(acc[q], xv.d[0], wv.d[0]);
                ffma2(acc[q], xv.d[1], wv.d[1]);
            }
        }

        int node = base + nloc;
        if (node < N_NODESC) {
            float dv = g_dinv[node];
            float r[8];
            #pragma unroll
            for (int q = 0; q < 8; q++) {
                float2 f = unpack2(acc[q]);
                r[q] = fmaxf(f.x + f.y + bias[q], 0.f);
            }
            *(float4*)&g_h0[(long)node * NH + j0]     = make_float4(r[0], r[1], r[2], r[3]);
            *(float4*)&g_h0[(long)node * NH + j0 + 4] = make_float4(r[4], r[5], r[6], r[7]);
            __half2 hh[4];
            #pragma unroll
            for (int q = 0; q < 4; q++)
                hh[q] = __floats2half2_rn(r[2 * q] * dv, r[2 * q + 1] * dv);
            *(uint2*)&g_h016[node * NH2 + (j0 >> 1)]     = *(uint2*)&hh[0];
            *(uint2*)&g_h016[node * NH2 + (j0 >> 1) + 2] = *(uint2*)&hh[2];
        }
    }
}

// ---------------- fused GCN2 layer: 64-node blocks (R6 scheme) ----------------
__global__ __launch_bounds__(256) void k_layer(const __half2* __restrict__ hin2,
                                               const float* __restrict__ h0,
                                               const float* __restrict__ W,
                                               __half2* __restrict__ hout2,
                                               int scale_out) {
    __shared__ float4 sW4[32 * 32];     // 16 KB packed W
    __shared__ float2 sMixT[32 * 66];   // 16.9 KB: [kp][n]

    for (int i = threadIdx.x; i < NH * NH; i += 256) {
        int k = i >> 6, j = i & 63;     // W row-major [k][j]
        int j2 = j >> 1, kp = k >> 1;
        int sel = ((j & 1) << 1) | (k & 1);
        ((float*)sW4)[j2 * 128 + (((kp + j2) & 31) << 2) + sel] = W[i];
    }

    int warp = threadIdx.x >> 5, lane = threadIdx.x & 31;
    int nodebase = blockIdx.x * 64;

    // gather 8 nodes per warp
    for (int m = 0; m < 8; m++) {
        int nl = warp * 8 + m;
        int node = nodebase + nl;
        float ax0 = 0.f, ay0 = 0.f, ax1 = 0.f, ay1 = 0.f;
        float mx = 0.f, my = 0.f;
        if (node < N_NODESC) {
            int s = g_rowptr[node], e = g_rowptr[node + 1];
            int i = s;
            for (; i + 4 <= e; i += 4) {
                int s0 = __ldg(&g_src[i]);
                int s1 = __ldg(&g_src[i + 1]);
                int s2 = __ldg(&g_src[i + 2]);
                int s3 = __ldg(&g_src[i + 3]);
                float2 v0 = __half22float2(__ldg(&hin2[s0 * NH2 + lane]));
                float2 v1 = __half22float2(__ldg(&hin2[s1 * NH2 + lane]));
                float2 v2 = __half22float2(__ldg(&hin2[s2 * NH2 + lane]));
                float2 v3 = __half22float2(__ldg(&hin2[s3 * NH2 + lane]));
                ax0 += v0.x; ay0 += v0.y;
                ax1 += v1.x; ay1 += v1.y;
                ax0 += v2.x; ay0 += v2.y;
                ax1 += v3.x; ay1 += v3.y;
            }
            for (; i < e; i++) {
                int s0 = __ldg(&g_src[i]);
                float2 v0 = __half22float2(__ldg(&hin2[s0 * NH2 + lane]));
                ax0 += v0.x; ay0 += v0.y;
            }
            float ax = ax0 + ax1, ay = ay0 + ay1;
            float2 h0v = *(const float2*)&h0[(long)node * NH + lane * 2];
            float dv = g_dinv[node];
            mx = fmaf(0.9f * dv, ax, 0.1f * h0v.x);
            my = fmaf(0.9f * dv, ay, 0.1f * h0v.y);
        }
        sMixT[lane * 66 + nl] = make_float2(mx, my);
    }
    __syncthreads();

    // matmul
    int j2 = lane, nq = warp;
    u64b acc0[8], acc1[8];
    #pragma unroll
    for (int n = 0; n < 8; n++) { acc0[n] = 0ULL; acc1[n] = 0ULL; }

    #pragma unroll 4
    for (int kp = 0; kp < 32; kp++) {
        F4U wv; wv.v = sW4[j2 * 32 + ((kp + j2) & 31)];
        const float2* mrow = &sMixT[kp * 66 + nq * 8];
        #pragma unroll
        for (int p = 0; p < 4; p++) {
            F4U mp; mp.v = *(const float4*)&mrow[2 * p];
            ffma2(acc0[2 * p],     mp.d[0], wv.d[0]);
            ffma2(acc1[2 * p],     mp.d[0], wv.d[1]);
            ffma2(acc0[2 * p + 1], mp.d[1], wv.d[0]);
            ffma2(acc1[2 * p + 1], mp.d[1], wv.d[1]);
        }
    }

    #pragma unroll
    for (int n = 0; n < 8; n++) {
        int node = nodebase + nq * 8 + n;
        if (node < N_NODESC) {
            float2 f0 = unpack2(acc0[n]);
            float2 f1 = unpack2(acc1[n]);
            float o0 = fmaxf(f0.x + f0.y, 0.f);
            float o1 = fmaxf(f1.x + f1.y, 0.f);
            float sc = scale_out ? g_dinv[node] : 1.0f;
            hout2[node * NH2 + j2] = __floats2half2_rn(o0 * sc, o1 * sc);
        }
    }
}

// ---------------- fc2: out = h @ W2^T + b2, split-K f32x2 ----------------
#define SW2S 66
#define SH2S 66
__global__ __launch_bounds__(320, 4) void k_fc2(const __half2* __restrict__ hin2,
                                                const float* __restrict__ w,
                                                const float* __restrict__ b,
                                                float* __restrict__ out) {
    __shared__ float sW[OUT_CHC * SW2S];
    __shared__ float sH[8 * SH2S];
    __shared__ float sB[OUT_CHC];
    for (int i = threadIdx.x; i < OUT_CHC * NH / 2; i += 320) {
        int j = i >> 5, kp = i & 31;
        *(float2*)&sW[j * SW2S + 2 * kp] = *(const float2*)&w[j * NH + 2 * kp];
    }
    if (threadIdx.x < OUT_CHC) sB[threadIdx.x] = b[threadIdx.x];
    __syncthreads();

    int tn = threadIdx.x / OUT_CHC;
    int j  = threadIdx.x % OUT_CHC;
    const int ngroups = N_NODESC / 8;

    for (int g = blockIdx.x; g < ngroups; g += gridDim.x) {
        int base = g * 8;
        __syncthreads();
        for (int i = threadIdx.x; i < 8 * NH2; i += 320) {
            int n = i >> 5, k2 = i & 31;
            float2 v = __half22float2(hin2[(base + n) * NH2 + k2]);
            *(float2*)&sH[n * SH2S + 2 * k2] = v;
        }
        __syncthreads();
        u64b acc = 0ULL;
        #pragma unroll 8
        for (int kp = 0; kp < NH / 2; kp++) {
            u64b a  = *(const u64b*)&sH[tn * SH2S + 2 * kp];
            u64b wv = *(const u64b*)&sW[j * SW2S + 2 * kp];
            ffma2(acc, a, wv);
        }
        float2 f = unpack2(acc);
        out[(long)(base + tn) * OUT_CHC + j] = f.x + f.y + sB[j];
    }
}

// ---------------- launch ----------------
extern "C" void kernel_launch(void* const* d_in, const int* in_sizes, int n_in,
                              void* d_out, int out_size) {
    const float* x      = (const float*)d_in[0];
    const int*   ei     = (const int*)d_in[1];
    const float* fc1_w  = (const float*)d_in[3];
    const float* fc1_b  = (const float*)d_in[4];
    const float* conv_w = (const float*)d_in[5];
    const float* fc2_w  = (const float*)d_in[6];
    const float* fc2_b  = (const float*)d_in[7];
    float*       out    = (float*)d_out;

    const int nb_nodes  = (N_NODESC + 255) / 256;
    const int nb_epairs = (N_EDGESC / 2 + 255) / 256;

    k_init<<<nb_nodes, 256>>>(ei);              // 0
    k_degree<<<nb_epairs, 256>>>(ei);           // 1
    k_scan_bsum<<<SCAN_NBLK, SCAN_CHUNK>>>();   // 2 (also dinv)
    k_fc1<<<1563, 512>>>(x, fc1_w, fc1_b);      // 3 (profiled slot)
    k_scan_top<<<1, 128>>>();
    k_scan_within<<<SCAN_NBLK, SCAN_CHUNK>>>();
    k_scatter<<<nb_epairs, 256>>>(ei);

    float* h0; __half2* h016; __half2* hA16; __half2* hB16;
    cudaGetSymbolAddress((void**)&h0,   g_h0);
    cudaGetSymbolAddress((void**)&h016, g_h016);
    cudaGetSymbolAddress((void**)&hA16, g_hA16);
    cudaGetSymbolAddress((void**)&hB16, g_hB16);

    const int nb_layer = (N_NODESC + 63) / 64;  // 1563
    k_layer<<<nb_layer, 256>>>(h016, h0, conv_w + 0 * NH * NH, hA16, 1);
    k_layer<<<nb_layer, 256>>>(hA16, h0, conv_w + 1 * NH * NH, hB16, 1);
    k_layer<<<nb_layer, 256>>>(hB16, h0, conv_w + 2 * NH * NH, hA16, 1);
    k_layer<<<nb_layer, 256>>>(hA16, h0, conv_w + 3 * NH * NH, hB16, 0);

    k_fc2<<<592, 320>>>(hB16, fc2_w, fc2_b, out);
}

// round 10
// speedup vs baseline: 1.1312x; 1.0974x over previous
#include <cuda_runtime.h>
#include <cuda_fp16.h>

#define N_NODESC 100000
#define N_EDGESC 1600000
#define IN_CH    128
#define NH       64
#define NH2      32
#define OUT_CHC  40

#define SCAN_CHUNK 1024
#define SCAN_NBLK  ((N_NODESC + SCAN_CHUNK - 1) / SCAN_CHUNK)   // 98

typedef unsigned long long u64b;

// ---------------- f32x2 packed helpers (bit-exact fp32, 2 MACs/instr) ----------------
__device__ __forceinline__ void ffma2(u64b& d, u64b a, u64b b) {
    asm("fma.rn.f32x2 %0, %1, %2, %0;" : "+l"(d) : "l"(a), "l"(b));
}
__device__ __forceinline__ float2 unpack2(u64b v) {
    float2 f; asm("mov.b64 {%0, %1}, %2;" : "=f"(f.x), "=f"(f.y) : "l"(v)); return f;
}
union F4U { float4 v; u64b d[2]; };

// ---------------- scratch ----------------
__device__ int     g_is64;
__device__ int     g_deg[N_NODESC];
__device__ int     g_rowptr[N_NODESC + 1];
__device__ int     g_cursor[N_NODESC];
__device__ int     g_bsum[SCAN_NBLK];
__device__ int     g_boff[SCAN_NBLK];
__device__ int     g_src[N_EDGESC];
__device__ float   g_dinv[N_NODESC];
__device__ float   g_h0[N_NODESC * NH];          // fp32 residual path (unscaled)
__device__ __half2 g_h016[N_NODESC * NH2];       // fp16, pre-scaled by dinv[node]
__device__ __half2 g_hA16[N_NODESC * NH2];
__device__ __half2 g_hB16[N_NODESC * NH2];

// ---------------- dtype detect + zero degree ----------------
__global__ void k_init(const int* __restrict__ ei) {
    int i = blockIdx.x * blockDim.x + threadIdx.x;
    if (i < N_NODESC) g_deg[i] = 0;
    if (blockIdx.x == 0 && threadIdx.x == 0) {
        int nz = 0;
        for (int j = 1; j < 512; j += 2) nz |= ei[j];
        g_is64 = (nz == 0) ? 1 : 0;
    }
}

// decode 2 edges per thread; histogram only
__global__ void k_degree(const int* __restrict__ ei) {
    int t = blockIdx.x * blockDim.x + threadIdx.x;
    if (t >= N_EDGESC / 2) return;
    int c0, c1;
    if (g_is64) {
        int4 cc = __ldg((const int4*)&ei[2 * N_EDGESC + 4 * t]);
        c0 = cc.x; c1 = cc.z;
    } else {
        int2 cc = __ldg((const int2*)&ei[N_EDGESC + 2 * t]);
        c0 = cc.x; c1 = cc.y;
    }
    if ((unsigned)c0 >= N_NODESC) c0 = 0;
    if ((unsigned)c1 >= N_NODESC) c1 = 0;
    atomicAdd(&g_deg[c0], 1);
    atomicAdd(&g_deg[c1], 1);
}

__global__ void k_scan_bsum() {
    __shared__ int s[SCAN_CHUNK];
    int t = threadIdx.x;
    int i = blockIdx.x * SCAN_CHUNK + t;
    int d = (i < N_NODESC) ? g_deg[i] : 0;
    if (i < N_NODESC) g_dinv[i] = (d > 0) ? rsqrtf((float)d) : 0.0f;
    s[t] = d;
    __syncthreads();
    for (int off = SCAN_CHUNK / 2; off > 0; off >>= 1) {
        if (t < off) s[t] += s[t + off];
        __syncthreads();
    }
    if (t == 0) g_bsum[blockIdx.x] = s[0];
}

__global__ void k_scan_top() {
    __shared__ int s[128];
    int t = threadIdx.x;
    s[t] = (t < SCAN_NBLK) ? g_bsum[t] : 0;
    __syncthreads();
    if (t == 0) {
        int acc = 0;
        for (int b = 0; b < SCAN_NBLK; b++) { int v = s[b]; s[b] = acc; acc += v; }
        g_rowptr[N_NODESC] = N_EDGESC;
    }
    __syncthreads();
    if (t < SCAN_NBLK) g_boff[t] = s[t];
}

__global__ void k_scan_within() {
    __shared__ int s[SCAN_CHUNK];
    int t = threadIdx.x;
    int i = blockIdx.x * SCAN_CHUNK + t;
    int v = (i < N_NODESC) ? g_deg[i] : 0;
    s[t] = v;
    __syncthreads();
    for (int off = 1; off < SCAN_CHUNK; off <<= 1) {
        int x = (t >= off) ? s[t - off] : 0;
        __syncthreads();
        s[t] += x;
        __syncthreads();
    }
    int excl = s[t] - v + g_boff[blockIdx.x];
    if (i < N_NODESC) { g_rowptr[i] = excl; g_cursor[i] = excl; }
}

// decode 2 edges per thread directly from ei; src index only
__global__ void k_scatter(const int* __restrict__ ei) {
    int t = blockIdx.x * blockDim.x + threadIdx.x;
    if (t >= N_EDGESC / 2) return;
    int r0, c0, r1, c1;
    if (g_is64) {
        int4 rr = __ldg((const int4*)&ei[4 * t]);
        int4 cc = __ldg((const int4*)&ei[2 * N_EDGESC + 4 * t]);
        r0 = rr.x; r1 = rr.z; c0 = cc.x; c1 = cc.z;
    } else {
        int2 rr = __ldg((const int2*)&ei[2 * t]);
        int2 cc = __ldg((const int2*)&ei[N_EDGESC + 2 * t]);
        r0 = rr.x; r1 = rr.y; c0 = cc.x; c1 = cc.y;
    }
    if ((unsigned)r0 >= N_NODESC) r0 = 0;
    if ((unsigned)r1 >= N_NODESC) r1 = 0;
    if ((unsigned)c0 >= N_NODESC) c0 = 0;
    if ((unsigned)c1 >= N_NODESC) c1 = 0;
    int p0 = atomicAdd(&g_cursor[c0], 1);
    if ((unsigned)p0 < N_EDGESC) g_src[p0] = r0;
    int p1 = atomicAdd(&g_cursor[c1], 1);
    if ((unsigned)p1 < N_EDGESC) g_src[p1] = r1;
}

// ---------------- fc1: h = relu(x @ W1^T + b1) via mma.sync fp16 ----------------
// Per block: 64 nodes x 64 outputs, K=128. 8 warps: m-tile = warp&3 (16 nodes),
// n-half = warp>>2 (32 cols = 2 x 16-wide units). Fragments via direct LDS.32:
// rows padded to 136 halves (272B) so 8 rows x 4 k-pairs cover all banks.
#define FC1_XS 136      // padded row stride in halves
__global__ __launch_bounds__(256) void k_fc1(const float* __restrict__ x,
                                             const float* __restrict__ w,
                                             const float* __restrict__ b) {
    __shared__ __half sX[64 * FC1_XS];      // 17.4 KB fp16 x tile
    __shared__ __half sW[64 * FC1_XS];      // 17.4 KB fp16 W
    __shared__ float  sBias[NH];
    __shared__ float  sDinv[64];

    int tid = threadIdx.x;
    int base = blockIdx.x * 64;

    // stage W (fp32 -> fp16), rows [j][k]
    {
        int row = tid >> 2, seg = tid & 3;
        #pragma unroll
        for (int it = 0; it < 4; it++) {
            int k = seg * 32 + it * 8;
            float4 v0 = __ldg((const float4*)&w[row * IN_CH + k]);
            float4 v1 = __ldg((const float4*)&w[row * IN_CH + k + 4]);
            __half2 h0 = __floats2half2_rn(v0.x, v0.y);
            __half2 h1 = __floats2half2_rn(v0.z, v0.w);
            __half2 h2 = __floats2half2_rn(v1.x, v1.y);
            __half2 h3 = __floats2half2_rn(v1.z, v1.w);
            uint4 u = make_uint4(*(unsigned*)&h0, *(unsigned*)&h1,
                                 *(unsigned*)&h2, *(unsigned*)&h3);
            *(uint4*)&sX[0] ; // no-op guard against compiler confusion
            *(uint4*)&sW[row * FC1_XS + k] = u;
        }
    }
    // stage x (fp32 -> fp16), 64 rows, clamp OOB
    {
        int row = tid >> 2, seg = tid & 3;
        long grow = (base + row < N_NODESC) ? (long)(base + row) : (long)(N_NODESC - 1);
        #pragma unroll
        for (int it = 0; it < 4; it++) {
            int k = seg * 32 + it * 8;
            float4 v0 = __ldg((const float4*)&x[grow * IN_CH + k]);
            float4 v1 = __ldg((const float4*)&x[grow * IN_CH + k + 4]);
            __half2 h0 = __floats2half2_rn(v0.x, v0.y);
            __half2 h1 = __floats2half2_rn(v0.z, v0.w);
            __half2 h2 = __floats2half2_rn(v1.x, v1.y);
            __half2 h3 = __floats2half2_rn(v1.z, v1.w);
            uint4 u = make_uint4(*(unsigned*)&h0, *(unsigned*)&h1,
                                 *(unsigned*)&h2, *(unsigned*)&h3);
            *(uint4*)&sX[row * FC1_XS + k] = u;
        }
    }
    if (tid < NH) sBias[tid] = b[tid];
    if (tid < 64) sDinv[tid] = (base + tid < N_NODESC) ? g_dinv[base + tid] : 0.f;
    __syncthreads();

    int warp = tid >> 5, lane = tid & 31;
    int g = lane >> 2, t = lane & 3;
    int m0 = (warp & 3) * 16;
    int nu = warp >> 2;                     // 0/1 -> cols [nu*32, nu*32+32)

    float d[2][2][4];
    #pragma unroll
    for (int u = 0; u < 2; u++)
        #pragma unroll
        for (int jm = 0; jm < 2; jm++)
            #pragma unroll
            for (int q = 0; q < 4; q++) d[u][jm][q] = 0.f;

    #pragma unroll
    for (int ks = 0; ks < 8; ks++) {
        int k0 = ks * 16;
        unsigned a0 = *(const unsigned*)&sX[(m0 + g) * FC1_XS + k0 + 2 * t];
        unsigned a1 = *(const unsigned*)&sX[(m0 + g + 8) * FC1_XS + k0 + 2 * t];
        unsigned a2 = *(const unsigned*)&sX[(m0 + g) * FC1_XS + k0 + 2 * t + 8];
        unsigned a3 = *(const unsigned*)&sX[(m0 + g + 8) * FC1_XS + k0 + 2 * t + 8];
        #pragma unroll
        for (int u = 0; u < 2; u++) {
            #pragma unroll
            for (int jm = 0; jm < 2; jm++) {
                int n8 = nu * 32 + u * 16 + jm * 8;
                unsigned b0 = *(const unsigned*)&sW[(n8 + g) * FC1_XS + k0 + 2 * t];
                unsigned b1 = *(const unsigned*)&sW[(n8 + g) * FC1_XS + k0 + 2 * t + 8];
                asm volatile(
                    "mma.sync.aligned.m16n8k16.row.col.f32.f16.f16.f32 "
                    "{%0,%1,%2,%3}, {%4,%5,%6,%7}, {%8,%9}, {%0,%1,%2,%3};"
                    : "+f"(d[u][jm][0]), "+f"(d[u][jm][1]),
                      "+f"(d[u][jm][2]), "+f"(d[u][jm][3])
                    : "r"(a0), "r"(a1), "r"(a2), "r"(a3), "r"(b0), "r"(b1));
            }
        }
    }

    // epilogue: bias + relu + fp32 store + dinv-scaled fp16 store
    int node0 = base + m0 + g;
    int node1 = node0 + 8;
    float dv0 = sDinv[m0 + g], dv1 = sDinv[m0 + g + 8];
    #pragma unroll
    for (int u = 0; u < 2; u++) {
        #pragma unroll
        for (int jm = 0; jm < 2; jm++) {
            int j0 = nu * 32 + u * 16 + jm * 8 + 2 * t;
            float2 bb = *(const float2*)&sBias[j0];
            float r00 = fmaxf(d[u][jm][0] + bb.x, 0.f);
            float r01 = fmaxf(d[u][jm][1] + bb.y, 0.f);
            float r10 = fmaxf(d[u][jm][2] + bb.x, 0.f);
            float r11 = fmaxf(d[u][jm][3] + bb.y, 0.f);
            if (node0 < N_NODESC) {
                *(float2*)&g_h0[(long)node0 * NH + j0] = make_float2(r00, r01);
                g_h016[node0 * NH2 + (j0 >> 1)] = __floats2half2_rn(r00 * dv0, r01 * dv0);
            }
            if (node1 < N_NODESC) {
                *(float2*)&g_h0[(long)node1 * NH + j0] = make_float2(r10, r11);
                g_h016[node1 * NH2 + (j0 >> 1)] = __floats2half2_rn(r10 * dv1, r11 * dv1);
            }
        }
    }
}

// ---------------- fused GCN2 layer: 64-node blocks (R6 scheme) ----------------
__global__ __launch_bounds__(256) void k_layer(const __half2* __restrict__ hin2,
                                               const float* __restrict__ h0,
                                               const float* __restrict__ W,
                                               __half2* __restrict__ hout2,
                                               int scale_out) {
    __shared__ float4 sW4[32 * 32];     // 16 KB packed W
    __shared__ float2 sMixT[32 * 66];   // 16.9 KB: [kp][n]

    for (int i = threadIdx.x; i < NH * NH; i += 256) {
        int k = i >> 6, j = i & 63;     // W row-major [k][j]
        int j2 = j >> 1, kp = k >> 1;
        int sel = ((j & 1) << 1) | (k & 1);
        ((float*)sW4)[j2 * 128 + (((kp + j2) & 31) << 2) + sel] = W[i];
    }

    int warp = threadIdx.x >> 5, lane = threadIdx.x & 31;
    int nodebase = blockIdx.x * 64;

    // gather 8 nodes per warp
    for (int m = 0; m < 8; m++) {
        int nl = warp * 8 + m;
        int node = nodebase + nl;
        float ax0 = 0.f, ay0 = 0.f, ax1 = 0.f, ay1 = 0.f;
        float mx = 0.f, my = 0.f;
        if (node < N_NODESC) {
            int s = g_rowptr[node], e = g_rowptr[node + 1];
            int i = s;
            for (; i + 4 <= e; i += 4) {
                int s0 = __ldg(&g_src[i]);
                int s1 = __ldg(&g_src[i + 1]);
                int s2 = __ldg(&g_src[i + 2]);
                int s3 = __ldg(&g_src[i + 3]);
                float2 v0 = __half22float2(__ldg(&hin2[s0 * NH2 + lane]));
                float2 v1 = __half22float2(__ldg(&hin2[s1 * NH2 + lane]));
                float2 v2 = __half22float2(__ldg(&hin2[s2 * NH2 + lane]));
                float2 v3 = __half22float2(__ldg(&hin2[s3 * NH2 + lane]));
                ax0 += v0.x; ay0 += v0.y;
                ax1 += v1.x; ay1 += v1.y;
                ax0 += v2.x; ay0 += v2.y;
                ax1 += v3.x; ay1 += v3.y;
            }
            for (; i < e; i++) {
                int s0 = __ldg(&g_src[i]);
                float2 v0 = __half22float2(__ldg(&hin2[s0 * NH2 + lane]));
                ax0 += v0.x; ay0 += v0.y;
            }
            float ax = ax0 + ax1, ay = ay0 + ay1;
            float2 h0v = *(const float2*)&h0[(long)node * NH + lane * 2];
            float dv = g_dinv[node];
            mx = fmaf(0.9f * dv, ax, 0.1f * h0v.x);
            my = fmaf(0.9f * dv, ay, 0.1f * h0v.y);
        }
        sMixT[lane * 66 + nl] = make_float2(mx, my);
    }
    __syncthreads();

    // matmul
    int j2 = lane, nq = warp;
    u64b acc0[8], acc1[8];
    #pragma unroll
    for (int n = 0; n < 8; n++) { acc0[n] = 0ULL; acc1[n] = 0ULL; }

    #pragma unroll 4
    for (int kp = 0; kp < 32; kp++) {
        F4U wv; wv.v = sW4[j2 * 32 + ((kp + j2) & 31)];
        const float2* mrow = &sMixT[kp * 66 + nq * 8];
        #pragma unroll
        for (int p = 0; p < 4; p++) {
            F4U mp; mp.v = *(const float4*)&mrow[2 * p];
            ffma2(acc0[2 * p],     mp.d[0], wv.d[0]);
            ffma2(acc1[2 * p],     mp.d[0], wv.d[1]);
            ffma2(acc0[2 * p + 1], mp.d[1], wv.d[0]);
            ffma2(acc1[2 * p + 1], mp.d[1], wv.d[1]);
        }
    }

    #pragma unroll
    for (int n = 0; n < 8; n++) {
        int node = nodebase + nq * 8 + n;
        if (node < N_NODESC) {
            float2 f0 = unpack2(acc0[n]);
            float2 f1 = unpack2(acc1[n]);
            float o0 = fmaxf(f0.x + f0.y, 0.f);
            float o1 = fmaxf(f1.x + f1.y, 0.f);
            float sc = scale_out ? g_dinv[node] : 1.0f;
            hout2[node * NH2 + j2] = __floats2half2_rn(o0 * sc, o1 * sc);
        }
    }
}

// ---------------- fc2: out = h @ W2^T + b2, split-K f32x2 ----------------
#define SW2S 66
#define SH2S 66
__global__ __launch_bounds__(320, 4) void k_fc2(const __half2* __restrict__ hin2,
                                                const float* __restrict__ w,
                                                const float* __restrict__ b,
                                                float* __restrict__ out) {
    __shared__ float sW[OUT_CHC * SW2S];
    __shared__ float sH[8 * SH2S];
    __shared__ float sB[OUT_CHC];
    for (int i = threadIdx.x; i < OUT_CHC * NH / 2; i += 320) {
        int j = i >> 5, kp = i & 31;
        *(float2*)&sW[j * SW2S + 2 * kp] = *(const float2*)&w[j * NH + 2 * kp];
    }
    if (threadIdx.x < OUT_CHC) sB[threadIdx.x] = b[threadIdx.x];
    __syncthreads();

    int tn = threadIdx.x / OUT_CHC;
    int j  = threadIdx.x % OUT_CHC;
    const int ngroups = N_NODESC / 8;

    for (int g = blockIdx.x; g < ngroups; g += gridDim.x) {
        int base = g * 8;
        __syncthreads();
        for (int i = threadIdx.x; i < 8 * NH2; i += 320) {
            int n = i >> 5, k2 = i & 31;
            float2 v = __half22float2(hin2[(base + n) * NH2 + k2]);
            *(float2*)&sH[n * SH2S + 2 * k2] = v;
        }
        __syncthreads();
        u64b acc = 0ULL;
        #pragma unroll 8
        for (int kp = 0; kp < NH / 2; kp++) {
            u64b a  = *(const u64b*)&sH[tn * SH2S + 2 * kp];
            u64b wv = *(const u64b*)&sW[j * SW2S + 2 * kp];
            ffma2(acc, a, wv);
        }
        float2 f = unpack2(acc);
        out[(long)(base + tn) * OUT_CHC + j] = f.x + f.y + sB[j];
    }
}

// ---------------- launch ----------------
extern "C" void kernel_launch(void* const* d_in, const int* in_sizes, int n_in,
                              void* d_out, int out_size) {
    const float* x      = (const float*)d_in[0];
    const int*   ei     = (const int*)d_in[1];
    const float* fc1_w  = (const float*)d_in[3];
    const float* fc1_b  = (const float*)d_in[4];
    const float* conv_w = (const float*)d_in[5];
    const float* fc2_w  = (const float*)d_in[6];
    const float* fc2_b  = (const float*)d_in[7];
    float*       out    = (float*)d_out;

    const int nb_nodes  = (N_NODESC + 255) / 256;
    const int nb_epairs = (N_EDGESC / 2 + 255) / 256;

    k_init<<<nb_nodes, 256>>>(ei);              // 0
    k_degree<<<nb_epairs, 256>>>(ei);           // 1
    k_scan_bsum<<<SCAN_NBLK, SCAN_CHUNK>>>();   // 2 (also dinv)
    k_fc1<<<1563, 256>>>(x, fc1_w, fc1_b);      // 3 (profiled slot)
    k_scan_top<<<1, 128>>>();
    k_scan_within<<<SCAN_NBLK, SCAN_CHUNK>>>();
    k_scatter<<<nb_epairs, 256>>>(ei);

    float* h0; __half2* h016; __half2* hA16; __half2* hB16;
    cudaGetSymbolAddress((void**)&h0,   g_h0);
    cudaGetSymbolAddress((void**)&h016, g_h016);
    cudaGetSymbolAddress((void**)&hA16, g_hA16);
    cudaGetSymbolAddress((void**)&hB16, g_hB16);

    const int nb_layer = (N_NODESC + 63) / 64;  // 1563
    k_layer<<<nb_layer, 256>>>(h016, h0, conv_w + 0 * NH * NH, hA16, 1);
    k_layer<<<nb_layer, 256>>>(hA16, h0, conv_w + 1 * NH * NH, hB16, 1);
    k_layer<<<nb_layer, 256>>>(hB16, h0, conv_w + 2 * NH * NH, hA16, 1);
    k_layer<<<nb_layer, 256>>>(hA16, h0, conv_w + 3 * NH * NH, hB16, 0);

    k_fc2<<<592, 320>>>(hB16, fc2_w, fc2_b, out);
}